// round 1
// baseline (speedup 1.0000x reference)
#include <cuda_runtime.h>
#include <math.h>

// Problem constants
#define BATCH    256
#define SEQ      176          // 8 time blocks x 22 joints
#define TIME_LEN 8
#define JOINTS   22
#define D_IN     128
#define H_NUM    8
#define H_DIM    32
#define D_MODEL  256          // H_NUM * H_DIM
#define M_TOTAL  (BATCH * SEQ)   // 45056
#define SCALE    0.17677669529663687f  // 1/sqrt(32)

// Scratch for projected q, k, v (layout [B*S, 256] row-major)
__device__ float g_q[(size_t)M_TOTAL * D_MODEL];
__device__ float g_k[(size_t)M_TOTAL * D_MODEL];
__device__ float g_v[(size_t)M_TOTAL * D_MODEL];

// ---------------------------------------------------------------------------
// Kernel 1: fused QKV projection.  out = x @ W + b  (ReLU on V).
// Logical GEMM: M=45056, K=128, N=768 (three 256-col matrices).
// Tiling: BM=64, BN=64, BK=32, 256 threads, 4x4 per thread.
// grid = (704, 12): blockIdx.y/4 selects matrix, %4 selects 64-col block.
// ---------------------------------------------------------------------------
#define BM 64
#define BN 64
#define BK 32

__global__ __launch_bounds__(256) void qkv_kernel(
    const float* __restrict__ x,
    const float* __restrict__ Wq, const float* __restrict__ bq,
    const float* __restrict__ Wk, const float* __restrict__ bk,
    const float* __restrict__ Wv, const float* __restrict__ bv)
{
    __shared__ float As[BM][BK + 1];   // +1 pad: conflict-free scalar access
    __shared__ float Bs[BK][BN];

    const int mtx = blockIdx.y >> 2;        // 0=q, 1=k, 2=v
    const int cb  = blockIdx.y & 3;
    const float* __restrict__ W    = (mtx == 0) ? Wq : (mtx == 1) ? Wk : Wv;
    const float* __restrict__ bias = (mtx == 0) ? bq : (mtx == 1) ? bk : bv;
    float* __restrict__ out        = (mtx == 0) ? g_q : (mtx == 1) ? g_k : g_v;

    const int row0 = blockIdx.x * BM;
    const int col0 = cb * BN;               // within the 256-col matrix
    const int tid  = threadIdx.x;
    const int tx   = tid & 15;              // 0..15 -> 4 cols each
    const int ty   = tid >> 4;              // 0..15 -> 4 rows each

    float acc[4][4];
#pragma unroll
    for (int i = 0; i < 4; ++i)
#pragma unroll
        for (int j = 0; j < 4; ++j) acc[i][j] = 0.0f;

    for (int k0 = 0; k0 < D_IN; k0 += BK) {
        // Load A tile: 64 rows x 32 k  (512 float4, 2 per thread)
#pragma unroll
        for (int it = 0; it < 2; ++it) {
            int idx = tid + it * 256;       // 0..511
            int r   = idx >> 3;             // row within tile
            int f   = idx & 7;              // which float4 along k
            float4 xa = *(const float4*)(x + (size_t)(row0 + r) * D_IN + k0 + f * 4);
            As[r][f * 4 + 0] = xa.x;
            As[r][f * 4 + 1] = xa.y;
            As[r][f * 4 + 2] = xa.z;
            As[r][f * 4 + 3] = xa.w;
        }
        // Load B tile: 32 k x 64 cols (512 float4, 2 per thread)
#pragma unroll
        for (int it = 0; it < 2; ++it) {
            int idx = tid + it * 256;
            int kk  = idx >> 4;             // 0..31
            int c4  = idx & 15;             // 0..15
            float4 wv4 = *(const float4*)(W + (size_t)(k0 + kk) * D_MODEL + col0 + c4 * 4);
            *(float4*)&Bs[kk][c4 * 4] = wv4;
        }
        __syncthreads();

#pragma unroll
        for (int kk = 0; kk < BK; ++kk) {
            float a0 = As[ty * 4 + 0][kk];
            float a1 = As[ty * 4 + 1][kk];
            float a2 = As[ty * 4 + 2][kk];
            float a3 = As[ty * 4 + 3][kk];
            float4 b4 = *(const float4*)&Bs[kk][tx * 4];
            acc[0][0] += a0 * b4.x; acc[0][1] += a0 * b4.y; acc[0][2] += a0 * b4.z; acc[0][3] += a0 * b4.w;
            acc[1][0] += a1 * b4.x; acc[1][1] += a1 * b4.y; acc[1][2] += a1 * b4.z; acc[1][3] += a1 * b4.w;
            acc[2][0] += a2 * b4.x; acc[2][1] += a2 * b4.y; acc[2][2] += a2 * b4.z; acc[2][3] += a2 * b4.w;
            acc[3][0] += a3 * b4.x; acc[3][1] += a3 * b4.y; acc[3][2] += a3 * b4.z; acc[3][3] += a3 * b4.w;
        }
        __syncthreads();
    }

    // Epilogue: bias add (+ ReLU for V), store
    const float4 bb = *(const float4*)(bias + col0 + tx * 4);
#pragma unroll
    for (int i = 0; i < 4; ++i) {
        float4 o;
        o.x = acc[i][0] + bb.x;
        o.y = acc[i][1] + bb.y;
        o.z = acc[i][2] + bb.z;
        o.w = acc[i][3] + bb.w;
        if (mtx == 2) {
            o.x = fmaxf(o.x, 0.0f); o.y = fmaxf(o.y, 0.0f);
            o.z = fmaxf(o.z, 0.0f); o.w = fmaxf(o.w, 0.0f);
        }
        *(float4*)(out + (size_t)(row0 + ty * 4 + i) * D_MODEL + col0 + tx * 4) = o;
    }
}

// ---------------------------------------------------------------------------
// Kernel 2: masked attention per (batch, head).
// One block per (b,h) = 2048 blocks, 192 threads; thread s (<176) owns query s.
// K, V tiles for this (b,h) live in smem; q and accumulator in registers.
// Softmax without running max: scores ~ N(0,1) for this data, exp() is safe.
// Masked entries (same time block, t != s) are skipped structurally.
// ---------------------------------------------------------------------------
__global__ __launch_bounds__(192) void attn_kernel(float* __restrict__ out)
{
    __shared__ float ks[SEQ][H_DIM];
    __shared__ float vs[SEQ][H_DIM];

    const int bh = blockIdx.x;
    const int b  = bh >> 3;
    const int h  = bh & 7;
    const int tid = threadIdx.x;

    // Cooperative load of K and V tiles (coalesced float4)
    {
        const float* kg = g_k + ((size_t)b * SEQ) * D_MODEL + h * H_DIM;
        const float* vg = g_v + ((size_t)b * SEQ) * D_MODEL + h * H_DIM;
        for (int idx = tid; idx < SEQ * 8; idx += 192) {
            int t = idx >> 3;
            int f = idx & 7;
            *(float4*)&ks[t][f * 4] = *(const float4*)(kg + (size_t)t * D_MODEL + f * 4);
            *(float4*)&vs[t][f * 4] = *(const float4*)(vg + (size_t)t * D_MODEL + f * 4);
        }
    }
    __syncthreads();

    const int s = tid;
    if (s >= SEQ) return;

    // Load q (pre-scaled by 1/sqrt(H_DIM))
    float q[H_DIM];
    {
        const float* qg = g_q + ((size_t)b * SEQ + s) * D_MODEL + h * H_DIM;
#pragma unroll
        for (int f = 0; f < 8; ++f) {
            float4 t4 = *(const float4*)(qg + f * 4);
            q[f * 4 + 0] = t4.x * SCALE;
            q[f * 4 + 1] = t4.y * SCALE;
            q[f * 4 + 2] = t4.z * SCALE;
            q[f * 4 + 3] = t4.w * SCALE;
        }
    }

    float l = 0.0f;
    float acc[H_DIM];
#pragma unroll
    for (int d = 0; d < H_DIM; ++d) acc[d] = 0.0f;

    const int sblk = s / JOINTS;

    for (int tb = 0; tb < TIME_LEN; ++tb) {
        const int tlo = (tb == sblk) ? s : tb * JOINTS;
        const int thi = (tb == sblk) ? s + 1 : tb * JOINTS + JOINTS;
        for (int t = tlo; t < thi; ++t) {
            // score = q . k[t]
            float p0 = 0.f, p1 = 0.f, p2 = 0.f, p3 = 0.f;
#pragma unroll
            for (int f = 0; f < 8; ++f) {
                float4 k4 = *(const float4*)&ks[t][f * 4];
                p0 += q[f * 4 + 0] * k4.x;
                p1 += q[f * 4 + 1] * k4.y;
                p2 += q[f * 4 + 2] * k4.z;
                p3 += q[f * 4 + 3] * k4.w;
            }
            const float sc = (p0 + p1) + (p2 + p3);
            const float p  = __expf(sc);
            l += p;
#pragma unroll
            for (int f = 0; f < 8; ++f) {
                float4 v4 = *(const float4*)&vs[t][f * 4];
                acc[f * 4 + 0] += p * v4.x;
                acc[f * 4 + 1] += p * v4.y;
                acc[f * 4 + 2] += p * v4.z;
                acc[f * 4 + 3] += p * v4.w;
            }
        }
    }

    const float inv = 1.0f / l;
    float* og = out + ((size_t)b * SEQ + s) * D_MODEL + h * H_DIM;
#pragma unroll
    for (int f = 0; f < 8; ++f) {
        float4 o;
        o.x = acc[f * 4 + 0] * inv;
        o.y = acc[f * 4 + 1] * inv;
        o.z = acc[f * 4 + 2] * inv;
        o.w = acc[f * 4 + 3] * inv;
        *(float4*)(og + f * 4) = o;
    }
}

// ---------------------------------------------------------------------------
extern "C" void kernel_launch(void* const* d_in, const int* in_sizes, int n_in,
                              void* d_out, int out_size)
{
    const float* x  = (const float*)d_in[0];
    const float* Wq = (const float*)d_in[1];
    const float* bq = (const float*)d_in[2];
    const float* Wk = (const float*)d_in[3];
    const float* bk = (const float*)d_in[4];
    const float* Wv = (const float*)d_in[5];
    const float* bv = (const float*)d_in[6];
    float* out = (float*)d_out;

    dim3 g1(M_TOTAL / BM, 12, 1);   // 704 x 12
    qkv_kernel<<<g1, 256>>>(x, Wq, bq, Wk, bk, Wv, bv);

    attn_kernel<<<BATCH * H_NUM, 192>>>(out);
}

// round 3
// speedup vs baseline: 1.2330x; 1.2330x over previous
#include <cuda_runtime.h>
#include <math.h>

// Problem constants
#define BATCH    256
#define SEQ      176          // 8 time blocks x 22 joints
#define TIME_LEN 8
#define JOINTS   22
#define D_IN     128
#define H_NUM    8
#define H_DIM    32
#define D_MODEL  256          // H_NUM * H_DIM
#define M_TOTAL  (BATCH * SEQ)   // 45056
#define SCALE    0.17677669529663687f  // 1/sqrt(32)

// Scratch for projected q, k, v (layout [B*S, 256] row-major)
__device__ float g_q[(size_t)M_TOTAL * D_MODEL];
__device__ float g_k[(size_t)M_TOTAL * D_MODEL];
__device__ float g_v[(size_t)M_TOTAL * D_MODEL];

// ---------------------------------------------------------------------------
// Kernel 1: fused QKV projection.  out = x @ W + b  (ReLU on V).
// GEMM per matrix: M=45056, K=128, N=256.
// Tiling: BM=128, BN=128, BK=16, 256 threads, 8x8 per thread.
// grid = (352, 6): blockIdx.y>>1 selects matrix, &1 selects 128-col half.
// A staged transposed in smem so per-kk loads are 2 x LDS.128 per operand.
// ---------------------------------------------------------------------------
#define BM 128
#define BN 128
#define BK 16
#define APAD 4   // As row pad (floats) to spread store banks

__global__ __launch_bounds__(256) void qkv_kernel(
    const float* __restrict__ x,
    const float* __restrict__ Wq, const float* __restrict__ bq,
    const float* __restrict__ Wk, const float* __restrict__ bk,
    const float* __restrict__ Wv, const float* __restrict__ bv)
{
    __shared__ float As[BK][BM + APAD];   // transposed A tile: [k][m]
    __shared__ float Bs[BK][BN];          // [k][n]

    const int mtx = blockIdx.y >> 1;        // 0=q, 1=k, 2=v
    const int cb  = blockIdx.y & 1;
    const float* __restrict__ W    = (mtx == 0) ? Wq : (mtx == 1) ? Wk : Wv;
    const float* __restrict__ bias = (mtx == 0) ? bq : (mtx == 1) ? bk : bv;
    float* __restrict__ out        = (mtx == 0) ? g_q : (mtx == 1) ? g_k : g_v;

    const int row0 = blockIdx.x * BM;
    const int col0 = cb * BN;
    const int tid  = threadIdx.x;
    const int tx   = tid & 15;              // n: 8 cols at tx*8
    const int ty   = tid >> 4;              // m: 8 rows at ty*8

    float acc[8][8];
#pragma unroll
    for (int i = 0; i < 8; ++i)
#pragma unroll
        for (int j = 0; j < 8; ++j) acc[i][j] = 0.0f;

    for (int k0 = 0; k0 < D_IN; k0 += BK) {
        // A tile: 128 rows x 16 k = 512 float4 reads, stored transposed
#pragma unroll
        for (int it = 0; it < 2; ++it) {
            int idx = tid + it * 256;       // 0..511
            int r   = idx >> 2;             // row within tile (0..127)
            int f   = idx & 3;              // float4 index along k (0..3)
            float4 xa = *(const float4*)(x + (size_t)(row0 + r) * D_IN + k0 + f * 4);
            As[f * 4 + 0][r] = xa.x;
            As[f * 4 + 1][r] = xa.y;
            As[f * 4 + 2][r] = xa.z;
            As[f * 4 + 3][r] = xa.w;
        }
        // B tile: 16 k x 128 n = 512 float4
#pragma unroll
        for (int it = 0; it < 2; ++it) {
            int idx = tid + it * 256;
            int kk  = idx >> 5;             // 0..15
            int c4  = idx & 31;             // 0..31
            float4 wv4 = *(const float4*)(W + (size_t)(k0 + kk) * D_MODEL + col0 + c4 * 4);
            *(float4*)&Bs[kk][c4 * 4] = wv4;
        }
        __syncthreads();

#pragma unroll
        for (int kk = 0; kk < BK; ++kk) {
            float4 a0 = *(const float4*)&As[kk][ty * 8];
            float4 a1 = *(const float4*)&As[kk][ty * 8 + 4];
            float4 b0 = *(const float4*)&Bs[kk][tx * 8];
            float4 b1 = *(const float4*)&Bs[kk][tx * 8 + 4];
            float a[8] = {a0.x, a0.y, a0.z, a0.w, a1.x, a1.y, a1.z, a1.w};
            float bb[8] = {b0.x, b0.y, b0.z, b0.w, b1.x, b1.y, b1.z, b1.w};
#pragma unroll
            for (int i = 0; i < 8; ++i)
#pragma unroll
                for (int j = 0; j < 8; ++j)
                    acc[i][j] += a[i] * bb[j];
        }
        __syncthreads();
    }

    // Epilogue: bias add (+ ReLU for V), store 8x8 per thread
    const float4 bb0 = *(const float4*)(bias + col0 + tx * 8);
    const float4 bb1 = *(const float4*)(bias + col0 + tx * 8 + 4);
    const float bv8[8] = {bb0.x, bb0.y, bb0.z, bb0.w, bb1.x, bb1.y, bb1.z, bb1.w};
#pragma unroll
    for (int i = 0; i < 8; ++i) {
        float r[8];
#pragma unroll
        for (int j = 0; j < 8; ++j) {
            r[j] = acc[i][j] + bv8[j];
            if (mtx == 2) r[j] = fmaxf(r[j], 0.0f);
        }
        float* op = out + (size_t)(row0 + ty * 8 + i) * D_MODEL + col0 + tx * 8;
        *(float4*)(op)     = make_float4(r[0], r[1], r[2], r[3]);
        *(float4*)(op + 4) = make_float4(r[4], r[5], r[6], r[7]);
    }
}

// ---------------------------------------------------------------------------
// Kernel 2: masked attention per (batch, head).
// One block per (b,h) = 2048 blocks, 96 threads (88 active).
// Thread p owns query pair s0 = (p/11)*22 + (p%11)*2 and s1 = s0+1
// (both in the same time block -> shared mask structure).
// Each k/v float4 LDS feeds BOTH queries: 16 LDS.128 per 128 FMA per t.
// Mask applied by predicated zeroing (uniform loop, no divergence).
// ---------------------------------------------------------------------------
__global__ __launch_bounds__(96, 4) void attn_kernel(float* __restrict__ out)
{
    __shared__ float ks[SEQ][H_DIM];
    __shared__ float vs[SEQ][H_DIM];

    const int bh = blockIdx.x;
    const int b  = bh >> 3;
    const int h  = bh & 7;
    const int tid = threadIdx.x;

    // Cooperative load of K and V tiles (coalesced float4)
    {
        const float* kg = g_k + ((size_t)b * SEQ) * D_MODEL + h * H_DIM;
        const float* vg = g_v + ((size_t)b * SEQ) * D_MODEL + h * H_DIM;
        for (int idx = tid; idx < SEQ * 8; idx += 96) {
            int t = idx >> 3;
            int f = idx & 7;
            *(float4*)&ks[t][f * 4] = *(const float4*)(kg + (size_t)t * D_MODEL + f * 4);
            *(float4*)&vs[t][f * 4] = *(const float4*)(vg + (size_t)t * D_MODEL + f * 4);
        }
    }
    __syncthreads();

    if (tid >= 88) return;

    const int pb = tid / 11;            // time block of both queries
    const int s0 = pb * JOINTS + (tid % 11) * 2;
    const int s1 = s0 + 1;

    // Load q0, q1 (pre-scaled by 1/sqrt(H_DIM))
    float q0[H_DIM], q1[H_DIM];
    {
        const float* qg0 = g_q + ((size_t)b * SEQ + s0) * D_MODEL + h * H_DIM;
        const float* qg1 = qg0 + D_MODEL;
#pragma unroll
        for (int f = 0; f < 8; ++f) {
            float4 t0 = *(const float4*)(qg0 + f * 4);
            float4 t1 = *(const float4*)(qg1 + f * 4);
            q0[f * 4 + 0] = t0.x * SCALE; q0[f * 4 + 1] = t0.y * SCALE;
            q0[f * 4 + 2] = t0.z * SCALE; q0[f * 4 + 3] = t0.w * SCALE;
            q1[f * 4 + 0] = t1.x * SCALE; q1[f * 4 + 1] = t1.y * SCALE;
            q1[f * 4 + 2] = t1.z * SCALE; q1[f * 4 + 3] = t1.w * SCALE;
        }
    }

    float l0 = 0.0f, l1 = 0.0f;
    float acc0[H_DIM], acc1[H_DIM];
#pragma unroll
    for (int d = 0; d < H_DIM; ++d) { acc0[d] = 0.0f; acc1[d] = 0.0f; }

    for (int tb = 0; tb < TIME_LEN; ++tb) {
        const bool diag = (tb == pb);
#pragma unroll 2
        for (int tj = 0; tj < JOINTS; ++tj) {
            const int t = tb * JOINTS + tj;

            // scores for both queries (4-way split chains for ILP)
            float a0 = 0.f, a1 = 0.f, a2 = 0.f, a3 = 0.f;
            float c0 = 0.f, c1 = 0.f, c2 = 0.f, c3 = 0.f;
#pragma unroll
            for (int f = 0; f < 8; ++f) {
                float4 k4 = *(const float4*)&ks[t][f * 4];
                a0 += q0[f * 4 + 0] * k4.x;
                a1 += q0[f * 4 + 1] * k4.y;
                a2 += q0[f * 4 + 2] * k4.z;
                a3 += q0[f * 4 + 3] * k4.w;
                c0 += q1[f * 4 + 0] * k4.x;
                c1 += q1[f * 4 + 1] * k4.y;
                c2 += q1[f * 4 + 2] * k4.z;
                c3 += q1[f * 4 + 3] * k4.w;
            }
            const float sc0 = (a0 + a1) + (a2 + a3);
            const float sc1 = (c0 + c1) + (c2 + c3);
            const float e0 = __expf(sc0);
            const float e1 = __expf(sc1);
            // mask: within own time block, only the diagonal survives
            const float p0 = (!diag || (t == s0)) ? e0 : 0.0f;
            const float p1 = (!diag || (t == s1)) ? e1 : 0.0f;
            l0 += p0;
            l1 += p1;
#pragma unroll
            for (int f = 0; f < 8; ++f) {
                float4 v4 = *(const float4*)&vs[t][f * 4];
                acc0[f * 4 + 0] += p0 * v4.x;
                acc0[f * 4 + 1] += p0 * v4.y;
                acc0[f * 4 + 2] += p0 * v4.z;
                acc0[f * 4 + 3] += p0 * v4.w;
                acc1[f * 4 + 0] += p1 * v4.x;
                acc1[f * 4 + 1] += p1 * v4.y;
                acc1[f * 4 + 2] += p1 * v4.z;
                acc1[f * 4 + 3] += p1 * v4.w;
            }
        }
    }

    const float inv0 = 1.0f / l0;
    const float inv1 = 1.0f / l1;
    float* og0 = out + ((size_t)b * SEQ + s0) * D_MODEL + h * H_DIM;
    float* og1 = og0 + D_MODEL;
#pragma unroll
    for (int f = 0; f < 8; ++f) {
        *(float4*)(og0 + f * 4) = make_float4(acc0[f * 4 + 0] * inv0, acc0[f * 4 + 1] * inv0,
                                              acc0[f * 4 + 2] * inv0, acc0[f * 4 + 3] * inv0);
        *(float4*)(og1 + f * 4) = make_float4(acc1[f * 4 + 0] * inv1, acc1[f * 4 + 1] * inv1,
                                              acc1[f * 4 + 2] * inv1, acc1[f * 4 + 3] * inv1);
    }
}

// ---------------------------------------------------------------------------
extern "C" void kernel_launch(void* const* d_in, const int* in_sizes, int n_in,
                              void* d_out, int out_size)
{
    const float* x  = (const float*)d_in[0];
    const float* Wq = (const float*)d_in[1];
    const float* bq = (const float*)d_in[2];
    const float* Wk = (const float*)d_in[3];
    const float* bk = (const float*)d_in[4];
    const float* Wv = (const float*)d_in[5];
    const float* bv = (const float*)d_in[6];
    float* out = (float*)d_out;

    dim3 g1(M_TOTAL / BM, 6, 1);   // 352 x 6
    qkv_kernel<<<g1, 256>>>(x, Wq, bq, Wk, bk, Wv, bv);

    attn_kernel<<<BATCH * H_NUM, 96>>>(out);
}

// round 5
// speedup vs baseline: 1.3110x; 1.0633x over previous
#include <cuda_runtime.h>
#include <math.h>

// Problem constants
#define BATCH    256
#define SEQ      176          // 8 time blocks x 22 joints
#define TIME_LEN 8
#define JOINTS   22
#define D_IN     128
#define H_NUM    8
#define H_DIM    32
#define D_MODEL  256          // H_NUM * H_DIM
#define M_TOTAL  (BATCH * SEQ)   // 45056
#define SCALE    0.17677669529663687f  // 1/sqrt(32)

typedef unsigned long long u64;

// ---- packed f32x2 helpers (FFMA2 pipe; only reachable via PTX) ------------
__device__ __forceinline__ u64 pk2(float a, float b) {
    u64 r; asm("mov.b64 %0, {%1, %2};" : "=l"(r) : "f"(a), "f"(b)); return r;
}
__device__ __forceinline__ void upk2(float& a, float& b, u64 v) {
    asm("mov.b64 {%0, %1}, %2;" : "=f"(a), "=f"(b) : "l"(v));
}
__device__ __forceinline__ u64 fma2(u64 a, u64 b, u64 c) {
    u64 d; asm("fma.rn.f32x2 %0, %1, %2, %3;" : "=l"(d) : "l"(a), "l"(b), "l"(c)); return d;
}
__device__ __forceinline__ u64 add2(u64 a, u64 b) {
    u64 d; asm("add.rn.f32x2 %0, %1, %2;" : "=l"(d) : "l"(a), "l"(b)); return d;
}
__device__ __forceinline__ u64 mul2(u64 a, u64 b) {
    u64 d; asm("mul.rn.f32x2 %0, %1, %2;" : "=l"(d) : "l"(a), "l"(b)); return d;
}

// Scratch for projected q, k, v (layout [B*S, 256] row-major)
__device__ float g_q[(size_t)M_TOTAL * D_MODEL];
__device__ float g_k[(size_t)M_TOTAL * D_MODEL];
__device__ float g_v[(size_t)M_TOTAL * D_MODEL];

// ---------------------------------------------------------------------------
// Kernel 1: fused QKV projection.  out = x @ W + b  (ReLU on V).
// GEMM per matrix: M=45056, K=128, N=256.
// BM=128, BN=128, BK=16, 256 threads, 8x8 per thread, f32x2 accumulators.
// ---------------------------------------------------------------------------
#define BM 128
#define BN 128
#define BK 16
#define APAD 4

__global__ __launch_bounds__(256) void qkv_kernel(
    const float* __restrict__ x,
    const float* __restrict__ Wq, const float* __restrict__ bq,
    const float* __restrict__ Wk, const float* __restrict__ bk,
    const float* __restrict__ Wv, const float* __restrict__ bv)
{
    __shared__ float As[BK][BM + APAD];   // transposed A tile: [k][m]
    __shared__ float Bs[BK][BN];          // [k][n]

    const int mtx = blockIdx.y >> 1;        // 0=q, 1=k, 2=v
    const int cb  = blockIdx.y & 1;
    const float* __restrict__ W    = (mtx == 0) ? Wq : (mtx == 1) ? Wk : Wv;
    const float* __restrict__ bias = (mtx == 0) ? bq : (mtx == 1) ? bk : bv;
    float* __restrict__ out        = (mtx == 0) ? g_q : (mtx == 1) ? g_k : g_v;

    const int row0 = blockIdx.x * BM;
    const int col0 = cb * BN;
    const int tid  = threadIdx.x;
    const int tx   = tid & 15;              // n: 8 cols at tx*8
    const int ty   = tid >> 4;              // m: 8 rows at ty*8

    u64 acc2[8][4];                         // 8 rows x 4 f32x2 col-pairs
#pragma unroll
    for (int i = 0; i < 8; ++i)
#pragma unroll
        for (int j = 0; j < 4; ++j) acc2[i][j] = 0ULL;

    for (int k0 = 0; k0 < D_IN; k0 += BK) {
        // A tile: 128 rows x 16 k, stored transposed
#pragma unroll
        for (int it = 0; it < 2; ++it) {
            int idx = tid + it * 256;
            int r   = idx >> 2;
            int f   = idx & 3;
            float4 xa = *(const float4*)(x + (size_t)(row0 + r) * D_IN + k0 + f * 4);
            As[f * 4 + 0][r] = xa.x;
            As[f * 4 + 1][r] = xa.y;
            As[f * 4 + 2][r] = xa.z;
            As[f * 4 + 3][r] = xa.w;
        }
        // B tile: 16 k x 128 n
#pragma unroll
        for (int it = 0; it < 2; ++it) {
            int idx = tid + it * 256;
            int kk  = idx >> 5;
            int c4  = idx & 31;
            float4 wv4 = *(const float4*)(W + (size_t)(k0 + kk) * D_MODEL + col0 + c4 * 4);
            *(float4*)&Bs[kk][c4 * 4] = wv4;
        }
        __syncthreads();

#pragma unroll
        for (int kk = 0; kk < BK; ++kk) {
            float4 a0 = *(const float4*)&As[kk][ty * 8];
            float4 a1 = *(const float4*)&As[kk][ty * 8 + 4];
            ulonglong2 b01 = *(const ulonglong2*)&Bs[kk][tx * 8];
            ulonglong2 b23 = *(const ulonglong2*)&Bs[kk][tx * 8 + 4];
            const u64 bp0 = b01.x, bp1 = b01.y, bp2 = b23.x, bp3 = b23.y;
            float a[8] = {a0.x, a0.y, a0.z, a0.w, a1.x, a1.y, a1.z, a1.w};
#pragma unroll
            for (int i = 0; i < 8; ++i) {
                const u64 ai = pk2(a[i], a[i]);
                acc2[i][0] = fma2(ai, bp0, acc2[i][0]);
                acc2[i][1] = fma2(ai, bp1, acc2[i][1]);
                acc2[i][2] = fma2(ai, bp2, acc2[i][2]);
                acc2[i][3] = fma2(ai, bp3, acc2[i][3]);
            }
        }
        __syncthreads();
    }

    // Epilogue: bias add (+ ReLU for V), store 8x8 per thread
    const float4 bb0 = *(const float4*)(bias + col0 + tx * 8);
    const float4 bb1 = *(const float4*)(bias + col0 + tx * 8 + 4);
    const float bv8[8] = {bb0.x, bb0.y, bb0.z, bb0.w, bb1.x, bb1.y, bb1.z, bb1.w};
#pragma unroll
    for (int i = 0; i < 8; ++i) {
        float r[8];
#pragma unroll
        for (int j = 0; j < 4; ++j) upk2(r[j * 2], r[j * 2 + 1], acc2[i][j]);
#pragma unroll
        for (int j = 0; j < 8; ++j) {
            r[j] = r[j] + bv8[j];
            if (mtx == 2) r[j] = fmaxf(r[j], 0.0f);
        }
        float* op = out + (size_t)(row0 + ty * 8 + i) * D_MODEL + col0 + tx * 8;
        *(float4*)(op)     = make_float4(r[0], r[1], r[2], r[3]);
        *(float4*)(op + 4) = make_float4(r[4], r[5], r[6], r[7]);
    }
}

// ---------------------------------------------------------------------------
// Kernel 2: masked attention per (batch, head).
// 2048 blocks, 96 threads (88 active), 2 queries per thread, f32x2 math.
// ---------------------------------------------------------------------------
__global__ __launch_bounds__(96, 4) void attn_kernel(float* __restrict__ out)
{
    __shared__ float ks[SEQ][H_DIM];
    __shared__ float vs[SEQ][H_DIM];

    const int bh = blockIdx.x;
    const int b  = bh >> 3;
    const int h  = bh & 7;
    const int tid = threadIdx.x;

    // Cooperative load of K and V tiles (coalesced float4)
    {
        const float* kg = g_k + ((size_t)b * SEQ) * D_MODEL + h * H_DIM;
        const float* vg = g_v + ((size_t)b * SEQ) * D_MODEL + h * H_DIM;
        for (int idx = tid; idx < SEQ * 8; idx += 96) {
            int t = idx >> 3;
            int f = idx & 7;
            *(float4*)&ks[t][f * 4] = *(const float4*)(kg + (size_t)t * D_MODEL + f * 4);
            *(float4*)&vs[t][f * 4] = *(const float4*)(vg + (size_t)t * D_MODEL + f * 4);
        }
    }
    __syncthreads();

    if (tid >= 88) return;

    const int pb = tid / 11;            // time block of both queries
    const int s0 = pb * JOINTS + (tid % 11) * 2;
    const int s1 = s0 + 1;

    // Load q0, q1 pre-scaled, packed as f32x2 pairs
    u64 q0p[16], q1p[16];
    {
        const float* qg0 = g_q + ((size_t)b * SEQ + s0) * D_MODEL + h * H_DIM;
        const float* qg1 = qg0 + D_MODEL;
#pragma unroll
        for (int f = 0; f < 8; ++f) {
            float4 t0 = *(const float4*)(qg0 + f * 4);
            float4 t1 = *(const float4*)(qg1 + f * 4);
            q0p[f * 2 + 0] = pk2(t0.x * SCALE, t0.y * SCALE);
            q0p[f * 2 + 1] = pk2(t0.z * SCALE, t0.w * SCALE);
            q1p[f * 2 + 0] = pk2(t1.x * SCALE, t1.y * SCALE);
            q1p[f * 2 + 1] = pk2(t1.z * SCALE, t1.w * SCALE);
        }
    }

    float l0 = 0.0f, l1 = 0.0f;
    u64 acc0p[16], acc1p[16];
#pragma unroll
    for (int d = 0; d < 16; ++d) { acc0p[d] = 0ULL; acc1p[d] = 0ULL; }

    for (int tb = 0; tb < TIME_LEN; ++tb) {
        const bool diag = (tb == pb);
#pragma unroll 2
        for (int tj = 0; tj < JOINTS; ++tj) {
            const int t = tb * JOINTS + tj;

            // scores for both queries: 2 f32x2 chains each
            u64 sa0 = 0ULL, sa1 = 0ULL, sb0 = 0ULL, sb1 = 0ULL;
#pragma unroll
            for (int f = 0; f < 8; ++f) {
                ulonglong2 kk2 = *(const ulonglong2*)&ks[t][f * 4];
                sa0 = fma2(q0p[f * 2 + 0], kk2.x, sa0);
                sa1 = fma2(q0p[f * 2 + 1], kk2.y, sa1);
                sb0 = fma2(q1p[f * 2 + 0], kk2.x, sb0);
                sb1 = fma2(q1p[f * 2 + 1], kk2.y, sb1);
            }
            float x0, x1, y0, y1;
            upk2(x0, x1, add2(sa0, sa1));
            upk2(y0, y1, add2(sb0, sb1));
            const float e0 = __expf(x0 + x1);
            const float e1 = __expf(y0 + y1);
            // mask: within own time block, only the diagonal survives
            const float p0 = (!diag || (t == s0)) ? e0 : 0.0f;
            const float p1 = (!diag || (t == s1)) ? e1 : 0.0f;
            l0 += p0;
            l1 += p1;
            const u64 pp0 = pk2(p0, p0);
            const u64 pp1 = pk2(p1, p1);
#pragma unroll
            for (int f = 0; f < 8; ++f) {
                ulonglong2 vv2 = *(const ulonglong2*)&vs[t][f * 4];
                acc0p[f * 2 + 0] = fma2(pp0, vv2.x, acc0p[f * 2 + 0]);
                acc0p[f * 2 + 1] = fma2(pp0, vv2.y, acc0p[f * 2 + 1]);
                acc1p[f * 2 + 0] = fma2(pp1, vv2.x, acc1p[f * 2 + 0]);
                acc1p[f * 2 + 1] = fma2(pp1, vv2.y, acc1p[f * 2 + 1]);
            }
        }
    }

    const u64 iv0 = pk2(1.0f / l0, 1.0f / l0);
    const u64 iv1 = pk2(1.0f / l1, 1.0f / l1);
    float* og0 = out + ((size_t)b * SEQ + s0) * D_MODEL + h * H_DIM;
    float* og1 = og0 + D_MODEL;
#pragma unroll
    for (int f = 0; f < 8; ++f) {
        ulonglong2 o0, o1;
        o0.x = mul2(acc0p[f * 2 + 0], iv0);
        o0.y = mul2(acc0p[f * 2 + 1], iv0);
        o1.x = mul2(acc1p[f * 2 + 0], iv1);
        o1.y = mul2(acc1p[f * 2 + 1], iv1);
        *(ulonglong2*)(og0 + f * 4) = o0;
        *(ulonglong2*)(og1 + f * 4) = o1;
    }
}

// ---------------------------------------------------------------------------
extern "C" void kernel_launch(void* const* d_in, const int* in_sizes, int n_in,
                              void* d_out, int out_size)
{
    const float* x  = (const float*)d_in[0];
    const float* Wq = (const float*)d_in[1];
    const float* bq = (const float*)d_in[2];
    const float* Wk = (const float*)d_in[3];
    const float* bk = (const float*)d_in[4];
    const float* Wv = (const float*)d_in[5];
    const float* bv = (const float*)d_in[6];
    float* out = (float*)d_out;

    dim3 g1(M_TOTAL / BM, 6, 1);   // 352 x 6
    qkv_kernel<<<g1, 256>>>(x, Wq, bq, Wk, bk, Wv, bv);

    attn_kernel<<<BATCH * H_NUM, 96>>>(out);
}

// round 10
// speedup vs baseline: 1.6060x; 1.2250x over previous
#include <cuda_runtime.h>
#include <cuda_bf16.h>
#include <math.h>
#include <stdint.h>

// Problem constants
#define BATCH    256
#define SEQ      176
#define TIME_LEN 8
#define JOINTS   22
#define D_IN     128
#define H_NUM    8
#define H_DIM    32
#define D_MODEL  256
#define M_TOTAL  (BATCH * SEQ)   // 45056
#define SCALE    0.17677669529663687f

typedef unsigned long long u64;

// ---- packed f32x2 helpers ----
__device__ __forceinline__ u64 pk2(float a, float b) {
    u64 r; asm("mov.b64 %0, {%1, %2};" : "=l"(r) : "f"(a), "f"(b)); return r;
}
__device__ __forceinline__ void upk2(float& a, float& b, u64 v) {
    asm("mov.b64 {%0, %1}, %2;" : "=f"(a), "=f"(b) : "l"(v));
}
__device__ __forceinline__ u64 fma2(u64 a, u64 b, u64 c) {
    u64 d; asm("fma.rn.f32x2 %0, %1, %2, %3;" : "=l"(d) : "l"(a), "l"(b), "l"(c)); return d;
}
__device__ __forceinline__ u64 add2(u64 a, u64 b) {
    u64 d; asm("add.rn.f32x2 %0, %1, %2;" : "=l"(d) : "l"(a), "l"(b)); return d;
}
__device__ __forceinline__ u64 mul2(u64 a, u64 b) {
    u64 d; asm("mul.rn.f32x2 %0, %1, %2;" : "=l"(d) : "l"(a), "l"(b)); return d;
}

// ---- warp MMA helpers (plain sm_80+ PTX; valid on sm_103 non-'a') ----
__device__ __forceinline__ uint32_t smem_u32(const void* p) {
    uint32_t a;
    asm("{ .reg .u64 t; cvta.to.shared.u64 t, %1; cvt.u32.u64 %0, t; }" : "=r"(a) : "l"(p));
    return a;
}
__device__ __forceinline__ void ldsm4(uint32_t& r0, uint32_t& r1, uint32_t& r2, uint32_t& r3,
                                      uint32_t addr) {
    asm volatile("ldmatrix.sync.aligned.m8n8.x4.shared.b16 {%0,%1,%2,%3}, [%4];"
                 : "=r"(r0), "=r"(r1), "=r"(r2), "=r"(r3) : "r"(addr));
}
__device__ __forceinline__ void mma16816(float* c, const uint32_t* a, const uint32_t* b) {
    asm volatile(
        "mma.sync.aligned.m16n8k16.row.col.f32.bf16.bf16.f32 "
        "{%0,%1,%2,%3}, {%4,%5,%6,%7}, {%8,%9}, {%0,%1,%2,%3};"
        : "+f"(c[0]), "+f"(c[1]), "+f"(c[2]), "+f"(c[3])
        : "r"(a[0]), "r"(a[1]), "r"(a[2]), "r"(a[3]), "r"(b[0]), "r"(b[1]));
}

// ---- device scratch ----
__device__ float g_q[(size_t)M_TOTAL * D_MODEL];
__device__ float g_k[(size_t)M_TOTAL * D_MODEL];
__device__ float g_v[(size_t)M_TOTAL * D_MODEL];
__device__ __nv_bfloat16 g_xhi[(size_t)M_TOTAL * D_IN];
__device__ __nv_bfloat16 g_xlo[(size_t)M_TOTAL * D_IN];
__device__ __nv_bfloat16 g_wthi[3 * D_MODEL * D_IN];   // transposed: [mtx][n][k]
__device__ __nv_bfloat16 g_wtlo[3 * D_MODEL * D_IN];

// ---------------------------------------------------------------------------
// Split kernels: fp32 -> bf16 hi/lo
// ---------------------------------------------------------------------------
__global__ __launch_bounds__(256) void split_x_kernel(const float* __restrict__ x)
{
    size_t i = ((size_t)blockIdx.x * 256 + threadIdx.x) * 4;
    float4 v = *(const float4*)(x + i);
    __nv_bfloat16 h0 = __float2bfloat16(v.x), h1 = __float2bfloat16(v.y);
    __nv_bfloat16 h2 = __float2bfloat16(v.z), h3 = __float2bfloat16(v.w);
    __nv_bfloat16 l0 = __float2bfloat16(v.x - __bfloat162float(h0));
    __nv_bfloat16 l1 = __float2bfloat16(v.y - __bfloat162float(h1));
    __nv_bfloat16 l2 = __float2bfloat16(v.z - __bfloat162float(h2));
    __nv_bfloat16 l3 = __float2bfloat16(v.w - __bfloat162float(h3));
    __nv_bfloat162 hA; hA.x = h0; hA.y = h1;
    __nv_bfloat162 hB; hB.x = h2; hB.y = h3;
    __nv_bfloat162 lA; lA.x = l0; lA.y = l1;
    __nv_bfloat162 lB; lB.x = l2; lB.y = l3;
    *(__nv_bfloat162*)(g_xhi + i)     = hA;
    *(__nv_bfloat162*)(g_xhi + i + 2) = hB;
    *(__nv_bfloat162*)(g_xlo + i)     = lA;
    *(__nv_bfloat162*)(g_xlo + i + 2) = lB;
}

// W [k=128][n=256] row-major -> Wt [n=256][k=128], split hi/lo. grid (256,3) x 128
__global__ __launch_bounds__(128) void split_w_kernel(
    const float* __restrict__ Wq, const float* __restrict__ Wk, const float* __restrict__ Wv)
{
    const int n = blockIdx.x;
    const int m = blockIdx.y;
    const int k = threadIdx.x;
    const float* W = (m == 0) ? Wq : (m == 1) ? Wk : Wv;
    float v = W[(size_t)k * D_MODEL + n];
    __nv_bfloat16 h = __float2bfloat16(v);
    __nv_bfloat16 l = __float2bfloat16(v - __bfloat162float(h));
    size_t o = (size_t)m * D_MODEL * D_IN + (size_t)n * D_IN + k;
    g_wthi[o] = h;
    g_wtlo[o] = l;
}

// ---------------------------------------------------------------------------
// QKV projection via warp-level mma.sync (bf16, 2-way split, 3 passes).
// Per CTA: M=128 x N=128 x K=128 fully smem-resident. grid=(352, 6).
// 8 warps: warp w -> (wm = w&1) 64-row group, (wn = w>>1) 32-col group.
// SMEM rows padded to 272 B (16B-aligned, conflict-free ldmatrix).
// ---------------------------------------------------------------------------
#define ROWB 272                    // bytes per smem row (128 bf16 + 8 pad)
#define SA_HI 0
#define SA_LO (128 * ROWB)
#define SB_HI (2 * 128 * ROWB)
#define SB_LO (3 * 128 * ROWB)
#define SMTOT (4 * 128 * ROWB)      // 139264 B

__global__ __launch_bounds__(256) void qkv_mma_kernel(
    const float* __restrict__ bq, const float* __restrict__ bk, const float* __restrict__ bv)
{
    extern __shared__ char smem[];
    const uint32_t sbase = smem_u32(smem);
    const int tid  = threadIdx.x;
    const int w    = tid >> 5;
    const int lane = tid & 31;
    const int mtx  = blockIdx.y >> 1;
    const int half = blockIdx.y & 1;
    const int row0 = blockIdx.x * 128;

    const float* bias = (mtx == 0) ? bq : (mtx == 1) ? bk : bv;
    float* outp       = (mtx == 0) ? g_q : (mtx == 1) ? g_k : g_v;
    const __nv_bfloat16* wth = g_wthi + (size_t)mtx * D_MODEL * D_IN + (size_t)half * 128 * D_IN;
    const __nv_bfloat16* wtl = g_wtlo + (size_t)mtx * D_MODEL * D_IN + (size_t)half * 128 * D_IN;

    // ---- load tiles: 2048 uint4 slots, 4 tiles each ----
    for (int idx = tid; idx < 2048; idx += 256) {
        const int r = idx >> 4;             // row (m for A, n for B)
        const int c = (idx & 15) * 8;       // bf16 col
        const uint32_t doff = (uint32_t)r * ROWB + c * 2;
        *(uint4*)(smem + SA_HI + doff) = *(const uint4*)(g_xhi + (size_t)(row0 + r) * D_IN + c);
        *(uint4*)(smem + SA_LO + doff) = *(const uint4*)(g_xlo + (size_t)(row0 + r) * D_IN + c);
        *(uint4*)(smem + SB_HI + doff) = *(const uint4*)(wth + (size_t)r * D_IN + c);
        *(uint4*)(smem + SB_LO + doff) = *(const uint4*)(wtl + (size_t)r * D_IN + c);
    }
    __syncthreads();

    const int wm = w & 1;                   // 0/1 -> rows 0-63 / 64-127
    const int wn = w >> 1;                  // 0..3 -> 32-col group

    float acc[4][4][4];
#pragma unroll
    for (int i = 0; i < 4; ++i)
#pragma unroll
        for (int j = 0; j < 4; ++j)
#pragma unroll
            for (int e = 0; e < 4; ++e) acc[i][j][e] = 0.0f;

    // ldmatrix lane addressing (byte offsets within a tile)
    // A: lanes -> row m0+(lane&15), col k0 + (lane>>4)*8
    const uint32_t a_lane = (uint32_t)(wm * 64 + (lane & 15)) * ROWB + ((lane >> 4) * 8) * 2;
    // B (.x4 = two n8 tiles): row n0 + (lane&7) + (lane>>4)*8, col k0 + ((lane>>3)&1)*8
    const uint32_t b_lane = (uint32_t)(wn * 32 + (lane & 7) + ((lane >> 4) * 8)) * ROWB
                          + (((lane >> 3) & 1) * 8) * 2;

    // 3 passes: (A_hi,B_hi), (A_hi,B_lo), (A_lo,B_hi)
    const uint32_t a_off[3] = {SA_HI, SA_HI, SA_LO};
    const uint32_t b_off[3] = {SB_HI, SB_LO, SB_HI};

#pragma unroll
    for (int pass = 0; pass < 3; ++pass) {
        const uint32_t abase = sbase + a_off[pass] + a_lane;
        const uint32_t bbase = sbase + b_off[pass] + b_lane;
#pragma unroll
        for (int ks = 0; ks < 8; ++ks) {
            const uint32_t ko = ks * 32;    // 16 bf16 = 32 bytes per k-step
            uint32_t af[4][4];
#pragma unroll
            for (int mt = 0; mt < 4; ++mt)
                ldsm4(af[mt][0], af[mt][1], af[mt][2], af[mt][3],
                      abase + ko + (uint32_t)(mt * 16) * ROWB);
            uint32_t bf[4][2];
#pragma unroll
            for (int nt2 = 0; nt2 < 2; ++nt2) {
                uint32_t r0, r1, r2, r3;
                ldsm4(r0, r1, r2, r3, bbase + ko + (uint32_t)(nt2 * 16) * ROWB);
                bf[nt2 * 2 + 0][0] = r0; bf[nt2 * 2 + 0][1] = r1;
                bf[nt2 * 2 + 1][0] = r2; bf[nt2 * 2 + 1][1] = r3;
            }
#pragma unroll
            for (int mt = 0; mt < 4; ++mt)
#pragma unroll
                for (int nt = 0; nt < 4; ++nt)
                    mma16816(acc[mt][nt], af[mt], bf[nt]);
        }
    }

    // ---- epilogue: bias (+ReLU for V), store fp32 ----
    const int rbase = row0 + wm * 64 + (lane >> 2);
    const int cbase = half * 128 + wn * 32 + 2 * (lane & 3);
#pragma unroll
    for (int mt = 0; mt < 4; ++mt) {
#pragma unroll
        for (int nt = 0; nt < 4; ++nt) {
            const int cg = cbase + nt * 8;
            const float b0 = bias[cg], b1 = bias[cg + 1];
            float v0 = acc[mt][nt][0] + b0;
            float v1 = acc[mt][nt][1] + b1;
            float v2 = acc[mt][nt][2] + b0;
            float v3 = acc[mt][nt][3] + b1;
            if (mtx == 2) {
                v0 = fmaxf(v0, 0.0f); v1 = fmaxf(v1, 0.0f);
                v2 = fmaxf(v2, 0.0f); v3 = fmaxf(v3, 0.0f);
            }
            const int rg = rbase + mt * 16;
            *(float2*)(outp + (size_t)rg * D_MODEL + cg)       = make_float2(v0, v1);
            *(float2*)(outp + (size_t)(rg + 8) * D_MODEL + cg) = make_float2(v2, v3);
        }
    }
}

// ---------------------------------------------------------------------------
// Kernel: masked attention per (batch, head) — SIMT f32x2 version (unchanged).
// ---------------------------------------------------------------------------
__global__ __launch_bounds__(96, 4) void attn_kernel(float* __restrict__ out)
{
    __shared__ float ks[SEQ][H_DIM];
    __shared__ float vs[SEQ][H_DIM];

    const int bh = blockIdx.x;
    const int b  = bh >> 3;
    const int h  = bh & 7;
    const int tid = threadIdx.x;

    {
        const float* kg = g_k + ((size_t)b * SEQ) * D_MODEL + h * H_DIM;
        const float* vg = g_v + ((size_t)b * SEQ) * D_MODEL + h * H_DIM;
        for (int idx = tid; idx < SEQ * 8; idx += 96) {
            int t = idx >> 3;
            int f = idx & 7;
            *(float4*)&ks[t][f * 4] = *(const float4*)(kg + (size_t)t * D_MODEL + f * 4);
            *(float4*)&vs[t][f * 4] = *(const float4*)(vg + (size_t)t * D_MODEL + f * 4);
        }
    }
    __syncthreads();

    if (tid >= 88) return;

    const int pb = tid / 11;
    const int s0 = pb * JOINTS + (tid % 11) * 2;
    const int s1 = s0 + 1;

    u64 q0p[16], q1p[16];
    {
        const float* qg0 = g_q + ((size_t)b * SEQ + s0) * D_MODEL + h * H_DIM;
        const float* qg1 = qg0 + D_MODEL;
#pragma unroll
        for (int f = 0; f < 8; ++f) {
            float4 t0 = *(const float4*)(qg0 + f * 4);
            float4 t1 = *(const float4*)(qg1 + f * 4);
            q0p[f * 2 + 0] = pk2(t0.x * SCALE, t0.y * SCALE);
            q0p[f * 2 + 1] = pk2(t0.z * SCALE, t0.w * SCALE);
            q1p[f * 2 + 0] = pk2(t1.x * SCALE, t1.y * SCALE);
            q1p[f * 2 + 1] = pk2(t1.z * SCALE, t1.w * SCALE);
        }
    }

    float l0 = 0.0f, l1 = 0.0f;
    u64 acc0p[16], acc1p[16];
#pragma unroll
    for (int d = 0; d < 16; ++d) { acc0p[d] = 0ULL; acc1p[d] = 0ULL; }

    for (int tb = 0; tb < TIME_LEN; ++tb) {
        const bool diag = (tb == pb);
#pragma unroll 2
        for (int tj = 0; tj < JOINTS; ++tj) {
            const int t = tb * JOINTS + tj;
            u64 sa0 = 0ULL, sa1 = 0ULL, sb0 = 0ULL, sb1 = 0ULL;
#pragma unroll
            for (int f = 0; f < 8; ++f) {
                ulonglong2 kk2 = *(const ulonglong2*)&ks[t][f * 4];
                sa0 = fma2(q0p[f * 2 + 0], kk2.x, sa0);
                sa1 = fma2(q0p[f * 2 + 1], kk2.y, sa1);
                sb0 = fma2(q1p[f * 2 + 0], kk2.x, sb0);
                sb1 = fma2(q1p[f * 2 + 1], kk2.y, sb1);
            }
            float x0, x1, y0, y1;
            upk2(x0, x1, add2(sa0, sa1));
            upk2(y0, y1, add2(sb0, sb1));
            const float e0 = __expf(x0 + x1);
            const float e1 = __expf(y0 + y1);
            const float p0 = (!diag || (t == s0)) ? e0 : 0.0f;
            const float p1 = (!diag || (t == s1)) ? e1 : 0.0f;
            l0 += p0;
            l1 += p1;
            const u64 pp0 = pk2(p0, p0);
            const u64 pp1 = pk2(p1, p1);
#pragma unroll
            for (int f = 0; f < 8; ++f) {
                ulonglong2 vv2 = *(const ulonglong2*)&vs[t][f * 4];
                acc0p[f * 2 + 0] = fma2(pp0, vv2.x, acc0p[f * 2 + 0]);
                acc0p[f * 2 + 1] = fma2(pp0, vv2.y, acc0p[f * 2 + 1]);
                acc1p[f * 2 + 0] = fma2(pp1, vv2.x, acc1p[f * 2 + 0]);
                acc1p[f * 2 + 1] = fma2(pp1, vv2.y, acc1p[f * 2 + 1]);
            }
        }
    }

    const u64 iv0 = pk2(1.0f / l0, 1.0f / l0);
    const u64 iv1 = pk2(1.0f / l1, 1.0f / l1);
    float* og0 = out + ((size_t)b * SEQ + s0) * D_MODEL + h * H_DIM;
    float* og1 = og0 + D_MODEL;
#pragma unroll
    for (int f = 0; f < 8; ++f) {
        ulonglong2 o0, o1;
        o0.x = mul2(acc0p[f * 2 + 0], iv0);
        o0.y = mul2(acc0p[f * 2 + 1], iv0);
        o1.x = mul2(acc1p[f * 2 + 0], iv1);
        o1.y = mul2(acc1p[f * 2 + 1], iv1);
        *(ulonglong2*)(og0 + f * 4) = o0;
        *(ulonglong2*)(og1 + f * 4) = o1;
    }
}

// ---------------------------------------------------------------------------
extern "C" void kernel_launch(void* const* d_in, const int* in_sizes, int n_in,
                              void* d_out, int out_size)
{
    const float* x  = (const float*)d_in[0];
    const float* Wq = (const float*)d_in[1];
    const float* bq = (const float*)d_in[2];
    const float* Wk = (const float*)d_in[3];
    const float* bk = (const float*)d_in[4];
    const float* Wv = (const float*)d_in[5];
    const float* bv = (const float*)d_in[6];
    float* out = (float*)d_out;

    static int smem_set = 0;
    if (!smem_set) {
        cudaFuncSetAttribute(qkv_mma_kernel, cudaFuncAttributeMaxDynamicSharedMemorySize, SMTOT);
        smem_set = 1;
    }

    split_x_kernel<<<(M_TOTAL * D_IN) / (256 * 4), 256>>>(x);
    split_w_kernel<<<dim3(D_MODEL, 3), 128>>>(Wq, Wk, Wv);
    qkv_mma_kernel<<<dim3(M_TOTAL / 128, 6), 256, SMTOT>>>(bq, bk, bv);
    attn_kernel<<<BATCH * H_NUM, 96>>>(out);
}

// round 11
// speedup vs baseline: 2.1481x; 1.3375x over previous
#include <cuda_runtime.h>
#include <cuda_bf16.h>
#include <math.h>
#include <stdint.h>

// Problem constants
#define BATCH    256
#define SEQ      176
#define TIME_LEN 8
#define JOINTS   22
#define D_IN     128
#define H_NUM    8
#define H_DIM    32
#define D_MODEL  256
#define M_TOTAL  (BATCH * SEQ)   // 45056
#define SCALE    0.17677669529663687f

typedef unsigned long long u64;

// ---- warp MMA helpers (plain sm_80+ PTX; valid on sm_103 non-'a') ----
__device__ __forceinline__ uint32_t smem_u32(const void* p) {
    uint32_t a;
    asm("{ .reg .u64 t; cvta.to.shared.u64 t, %1; cvt.u32.u64 %0, t; }" : "=r"(a) : "l"(p));
    return a;
}
__device__ __forceinline__ void ldsm4(uint32_t& r0, uint32_t& r1, uint32_t& r2, uint32_t& r3,
                                      uint32_t addr) {
    asm volatile("ldmatrix.sync.aligned.m8n8.x4.shared.b16 {%0,%1,%2,%3}, [%4];"
                 : "=r"(r0), "=r"(r1), "=r"(r2), "=r"(r3) : "r"(addr));
}
__device__ __forceinline__ void mma16816(float* c, const uint32_t* a, const uint32_t* b) {
    asm volatile(
        "mma.sync.aligned.m16n8k16.row.col.f32.bf16.bf16.f32 "
        "{%0,%1,%2,%3}, {%4,%5,%6,%7}, {%8,%9}, {%0,%1,%2,%3};"
        : "+f"(c[0]), "+f"(c[1]), "+f"(c[2]), "+f"(c[3])
        : "r"(a[0]), "r"(a[1]), "r"(a[2]), "r"(a[3]), "r"(b[0]), "r"(b[1]));
}

// ---- device scratch ----
__device__ float g_q[(size_t)M_TOTAL * D_MODEL];
__device__ float g_k[(size_t)M_TOTAL * D_MODEL];
__device__ float g_v[(size_t)M_TOTAL * D_MODEL];
__device__ __nv_bfloat16 g_xhi[(size_t)M_TOTAL * D_IN];
__device__ __nv_bfloat16 g_xlo[(size_t)M_TOTAL * D_IN];
__device__ __nv_bfloat16 g_wthi[3 * D_MODEL * D_IN];   // transposed: [mtx][n][k]
__device__ __nv_bfloat16 g_wtlo[3 * D_MODEL * D_IN];

// ---------------------------------------------------------------------------
// Split kernels: fp32 -> bf16 hi/lo
// ---------------------------------------------------------------------------
__global__ __launch_bounds__(256) void split_x_kernel(const float* __restrict__ x)
{
    size_t i = ((size_t)blockIdx.x * 256 + threadIdx.x) * 4;
    float4 v = *(const float4*)(x + i);
    __nv_bfloat16 h0 = __float2bfloat16(v.x), h1 = __float2bfloat16(v.y);
    __nv_bfloat16 h2 = __float2bfloat16(v.z), h3 = __float2bfloat16(v.w);
    __nv_bfloat16 l0 = __float2bfloat16(v.x - __bfloat162float(h0));
    __nv_bfloat16 l1 = __float2bfloat16(v.y - __bfloat162float(h1));
    __nv_bfloat16 l2 = __float2bfloat16(v.z - __bfloat162float(h2));
    __nv_bfloat16 l3 = __float2bfloat16(v.w - __bfloat162float(h3));
    __nv_bfloat162 hA; hA.x = h0; hA.y = h1;
    __nv_bfloat162 hB; hB.x = h2; hB.y = h3;
    __nv_bfloat162 lA; lA.x = l0; lA.y = l1;
    __nv_bfloat162 lB; lB.x = l2; lB.y = l3;
    *(__nv_bfloat162*)(g_xhi + i)     = hA;
    *(__nv_bfloat162*)(g_xhi + i + 2) = hB;
    *(__nv_bfloat162*)(g_xlo + i)     = lA;
    *(__nv_bfloat162*)(g_xlo + i + 2) = lB;
}

// W [k=128][n=256] row-major -> Wt [n=256][k=128], split hi/lo. grid (256,3) x 128
__global__ __launch_bounds__(128) void split_w_kernel(
    const float* __restrict__ Wq, const float* __restrict__ Wk, const float* __restrict__ Wv)
{
    const int n = blockIdx.x;
    const int m = blockIdx.y;
    const int k = threadIdx.x;
    const float* W = (m == 0) ? Wq : (m == 1) ? Wk : Wv;
    float v = W[(size_t)k * D_MODEL + n];
    __nv_bfloat16 h = __float2bfloat16(v);
    __nv_bfloat16 l = __float2bfloat16(v - __bfloat162float(h));
    size_t o = (size_t)m * D_MODEL * D_IN + (size_t)n * D_IN + k;
    g_wthi[o] = h;
    g_wtlo[o] = l;
}

// ---------------------------------------------------------------------------
// QKV projection via warp-level mma.sync (bf16, 2-way split, 3 passes).
// Per CTA: M=128 x N=128 x K=128 fully smem-resident. grid=(352, 6).
// ---------------------------------------------------------------------------
#define ROWB 272                    // bytes per smem row (128 bf16 + 8 pad)
#define SA_HI 0
#define SA_LO (128 * ROWB)
#define SB_HI (2 * 128 * ROWB)
#define SB_LO (3 * 128 * ROWB)
#define SMTOT (4 * 128 * ROWB)      // 139264 B

__global__ __launch_bounds__(256) void qkv_mma_kernel(
    const float* __restrict__ bq, const float* __restrict__ bk, const float* __restrict__ bv)
{
    extern __shared__ char smem[];
    const uint32_t sbase = smem_u32(smem);
    const int tid  = threadIdx.x;
    const int w    = tid >> 5;
    const int lane = tid & 31;
    const int mtx  = blockIdx.y >> 1;
    const int half = blockIdx.y & 1;
    const int row0 = blockIdx.x * 128;

    const float* bias = (mtx == 0) ? bq : (mtx == 1) ? bk : bv;
    float* outp       = (mtx == 0) ? g_q : (mtx == 1) ? g_k : g_v;
    const __nv_bfloat16* wth = g_wthi + (size_t)mtx * D_MODEL * D_IN + (size_t)half * 128 * D_IN;
    const __nv_bfloat16* wtl = g_wtlo + (size_t)mtx * D_MODEL * D_IN + (size_t)half * 128 * D_IN;

    for (int idx = tid; idx < 2048; idx += 256) {
        const int r = idx >> 4;
        const int c = (idx & 15) * 8;
        const uint32_t doff = (uint32_t)r * ROWB + c * 2;
        *(uint4*)(smem + SA_HI + doff) = *(const uint4*)(g_xhi + (size_t)(row0 + r) * D_IN + c);
        *(uint4*)(smem + SA_LO + doff) = *(const uint4*)(g_xlo + (size_t)(row0 + r) * D_IN + c);
        *(uint4*)(smem + SB_HI + doff) = *(const uint4*)(wth + (size_t)r * D_IN + c);
        *(uint4*)(smem + SB_LO + doff) = *(const uint4*)(wtl + (size_t)r * D_IN + c);
    }
    __syncthreads();

    const int wm = w & 1;
    const int wn = w >> 1;

    float acc[4][4][4];
#pragma unroll
    for (int i = 0; i < 4; ++i)
#pragma unroll
        for (int j = 0; j < 4; ++j)
#pragma unroll
            for (int e = 0; e < 4; ++e) acc[i][j][e] = 0.0f;

    const uint32_t a_lane = (uint32_t)(wm * 64 + (lane & 15)) * ROWB + ((lane >> 4) * 8) * 2;
    const uint32_t b_lane = (uint32_t)(wn * 32 + (lane & 7) + ((lane >> 4) * 8)) * ROWB
                          + (((lane >> 3) & 1) * 8) * 2;

    const uint32_t a_off[3] = {SA_HI, SA_HI, SA_LO};
    const uint32_t b_off[3] = {SB_HI, SB_LO, SB_HI};

#pragma unroll
    for (int pass = 0; pass < 3; ++pass) {
        const uint32_t abase = sbase + a_off[pass] + a_lane;
        const uint32_t bbase = sbase + b_off[pass] + b_lane;
#pragma unroll
        for (int ks = 0; ks < 8; ++ks) {
            const uint32_t ko = ks * 32;
            uint32_t af[4][4];
#pragma unroll
            for (int mt = 0; mt < 4; ++mt)
                ldsm4(af[mt][0], af[mt][1], af[mt][2], af[mt][3],
                      abase + ko + (uint32_t)(mt * 16) * ROWB);
            uint32_t bf[4][2];
#pragma unroll
            for (int nt2 = 0; nt2 < 2; ++nt2) {
                uint32_t r0, r1, r2, r3;
                ldsm4(r0, r1, r2, r3, bbase + ko + (uint32_t)(nt2 * 16) * ROWB);
                bf[nt2 * 2 + 0][0] = r0; bf[nt2 * 2 + 0][1] = r1;
                bf[nt2 * 2 + 1][0] = r2; bf[nt2 * 2 + 1][1] = r3;
            }
#pragma unroll
            for (int mt = 0; mt < 4; ++mt)
#pragma unroll
                for (int nt = 0; nt < 4; ++nt)
                    mma16816(acc[mt][nt], af[mt], bf[nt]);
        }
    }

    const int rbase = row0 + wm * 64 + (lane >> 2);
    const int cbase = half * 128 + wn * 32 + 2 * (lane & 3);
#pragma unroll
    for (int mt = 0; mt < 4; ++mt) {
#pragma unroll
        for (int nt = 0; nt < 4; ++nt) {
            const int cg = cbase + nt * 8;
            const float b0 = bias[cg], b1 = bias[cg + 1];
            float v0 = acc[mt][nt][0] + b0;
            float v1 = acc[mt][nt][1] + b1;
            float v2 = acc[mt][nt][2] + b0;
            float v3 = acc[mt][nt][3] + b1;
            if (mtx == 2) {
                v0 = fmaxf(v0, 0.0f); v1 = fmaxf(v1, 0.0f);
                v2 = fmaxf(v2, 0.0f); v3 = fmaxf(v3, 0.0f);
            }
            const int rg = rbase + mt * 16;
            *(float2*)(outp + (size_t)rg * D_MODEL + cg)       = make_float2(v0, v1);
            *(float2*)(outp + (size_t)(rg + 8) * D_MODEL + cg) = make_float2(v2, v3);
        }
    }
}

// ---------------------------------------------------------------------------
// Tensor-core attention: one CTA per (b,h), 4 warps, flash-style streaming.
// Q/K [176][32] + V^T [32][176] staged in smem as bf16 hi/lo.
// S = QK^T 3-pass split; mask+exp in c-fragments; register repack S->A frag;
// P*V 3-pass split accumulated in registers; row sums via quad shfl.
// M padded to 192 (tile 11 zero rows). 11 t-chunks of 16.
// ---------------------------------------------------------------------------
// smem element offsets (bf16)
#define AQH 0
#define AQL (192 * 40)
#define AKH (2 * 192 * 40)
#define AKL (AKH + 176 * 40)
#define AVH (AKL + 176 * 40)
#define AVL (AVH + 32 * 184)
#define ASMEM_ELEMS (AVL + 32 * 184)     // 41216 elems
#define ASMEM_BYTES (ASMEM_ELEMS * 2)    // 82432 B

__global__ __launch_bounds__(128) void attn_mma_kernel(float* __restrict__ out)
{
    extern __shared__ char smemc[];
    __nv_bfloat16* sm = (__nv_bfloat16*)smemc;

    const int bh = blockIdx.x;
    const int b  = bh >> 3;
    const int h  = bh & 7;
    const int tid  = threadIdx.x;
    const int w    = tid >> 5;
    const int lane = tid & 31;

    // ---- stage q (scaled), k, v^T as bf16 hi/lo ----
    {
        const float* qg = g_q + ((size_t)b * SEQ) * D_MODEL + h * H_DIM;
        const float* kg = g_k + ((size_t)b * SEQ) * D_MODEL + h * H_DIM;
        const float* vg = g_v + ((size_t)b * SEQ) * D_MODEL + h * H_DIM;
        for (int idx = tid; idx < SEQ * 8; idx += 128) {
            const int t = idx >> 3, f = idx & 7;
            // q with scale
            float4 q4 = *(const float4*)(qg + (size_t)t * D_MODEL + f * 4);
            q4.x *= SCALE; q4.y *= SCALE; q4.z *= SCALE; q4.w *= SCALE;
            {
                __nv_bfloat162 h0 = __floats2bfloat162_rn(q4.x, q4.y);
                __nv_bfloat162 h1 = __floats2bfloat162_rn(q4.z, q4.w);
                __nv_bfloat162 l0 = __floats2bfloat162_rn(q4.x - __bfloat162float(h0.x),
                                                          q4.y - __bfloat162float(h0.y));
                __nv_bfloat162 l1 = __floats2bfloat162_rn(q4.z - __bfloat162float(h1.x),
                                                          q4.w - __bfloat162float(h1.y));
                *(uint2*)(sm + AQH + t * 40 + f * 4) = make_uint2(*(uint32_t*)&h0, *(uint32_t*)&h1);
                *(uint2*)(sm + AQL + t * 40 + f * 4) = make_uint2(*(uint32_t*)&l0, *(uint32_t*)&l1);
            }
            // k
            float4 k4 = *(const float4*)(kg + (size_t)t * D_MODEL + f * 4);
            {
                __nv_bfloat162 h0 = __floats2bfloat162_rn(k4.x, k4.y);
                __nv_bfloat162 h1 = __floats2bfloat162_rn(k4.z, k4.w);
                __nv_bfloat162 l0 = __floats2bfloat162_rn(k4.x - __bfloat162float(h0.x),
                                                          k4.y - __bfloat162float(h0.y));
                __nv_bfloat162 l1 = __floats2bfloat162_rn(k4.z - __bfloat162float(h1.x),
                                                          k4.w - __bfloat162float(h1.y));
                *(uint2*)(sm + AKH + t * 40 + f * 4) = make_uint2(*(uint32_t*)&h0, *(uint32_t*)&h1);
                *(uint2*)(sm + AKL + t * 40 + f * 4) = make_uint2(*(uint32_t*)&l0, *(uint32_t*)&l1);
            }
            // v transposed scatter
            float4 v4 = *(const float4*)(vg + (size_t)t * D_MODEL + f * 4);
            float vv[4] = {v4.x, v4.y, v4.z, v4.w};
#pragma unroll
            for (int j = 0; j < 4; ++j) {
                const int d = f * 4 + j;
                __nv_bfloat16 hb = __float2bfloat16(vv[j]);
                sm[AVH + d * 184 + t] = hb;
                sm[AVL + d * 184 + t] = __float2bfloat16(vv[j] - __bfloat162float(hb));
            }
        }
        // zero Q pad rows 176..191
        {
            const int t = 176 + (tid >> 3), f = tid & 7;
            *(uint2*)(sm + AQH + t * 40 + f * 4) = make_uint2(0u, 0u);
            *(uint2*)(sm + AQL + t * 40 + f * 4) = make_uint2(0u, 0u);
        }
    }
    __syncthreads();

    const uint32_t sb = smem_u32(sm);
    const uint32_t qh_b = sb + AQH * 2, ql_b = sb + AQL * 2;
    const uint32_t kh_b = sb + AKH * 2, kl_b = sb + AKL * 2;
    const uint32_t vh_b = sb + AVH * 2, vl_b = sb + AVL * 2;

    // lane addressing
    const uint32_t arow  = (uint32_t)(lane & 15);
    const uint32_t acolb = (uint32_t)((lane >> 4) * 16);
    const uint32_t brow  = (uint32_t)((lane & 7) + ((lane >> 4) * 8));
    const uint32_t bcolb = (uint32_t)(((lane >> 3) & 1) * 16);

    float accPV[3][4][4];
#pragma unroll
    for (int i = 0; i < 3; ++i)
#pragma unroll
        for (int j = 0; j < 4; ++j)
#pragma unroll
            for (int e = 0; e < 4; ++e) accPV[i][j][e] = 0.0f;
    float lsum[3][2] = {{0, 0}, {0, 0}, {0, 0}};

    const int r_off = lane >> 2;
    const int c_off = 2 * (lane & 3);

    for (int tc = 0; tc < 11; ++tc) {
        const int t0 = tc * 16;

        uint32_t khf[2][4], klf[2][4];
#pragma unroll
        for (int d0 = 0; d0 < 2; ++d0) {
            const uint32_t off = (t0 + brow) * 80 + bcolb + d0 * 32;
            ldsm4(khf[d0][0], khf[d0][1], khf[d0][2], khf[d0][3], kh_b + off);
            ldsm4(klf[d0][0], klf[d0][1], klf[d0][2], klf[d0][3], kl_b + off);
        }
        uint32_t vhf[2][4], vlf[2][4];
#pragma unroll
        for (int dp = 0; dp < 2; ++dp) {
            const uint32_t off = (dp * 16 + brow) * 368 + (uint32_t)t0 * 2 + bcolb;
            ldsm4(vhf[dp][0], vhf[dp][1], vhf[dp][2], vhf[dp][3], vh_b + off);
            ldsm4(vlf[dp][0], vlf[dp][1], vlf[dp][2], vlf[dp][3], vl_b + off);
        }

        // t-block metadata for masking (same for all m-tiles)
        const int tA = t0 + c_off;            // ntile 0, even col
        const int tbA0 = tA / 22,       tbB0 = (tA + 1) / 22;
        const int tbA1 = (tA + 8) / 22, tbB1 = (tA + 9) / 22;

#pragma unroll
        for (int i = 0; i < 3; ++i) {
            const int m0 = (3 * w + i) * 16;
            float s[2][4];
#pragma unroll
            for (int nt = 0; nt < 2; ++nt)
#pragma unroll
                for (int e = 0; e < 4; ++e) s[nt][e] = 0.0f;

            uint32_t a[2][4];
            const uint32_t aoff = (m0 + arow) * 80 + acolb;
            // pass 1+2: A_hi x (K_hi, K_lo)
#pragma unroll
            for (int d0 = 0; d0 < 2; ++d0)
                ldsm4(a[d0][0], a[d0][1], a[d0][2], a[d0][3], qh_b + aoff + d0 * 32);
#pragma unroll
            for (int d0 = 0; d0 < 2; ++d0)
#pragma unroll
                for (int nt = 0; nt < 2; ++nt) {
                    mma16816(s[nt], a[d0], &khf[d0][nt * 2]);
                    mma16816(s[nt], a[d0], &klf[d0][nt * 2]);
                }
            // pass 3: A_lo x K_hi
#pragma unroll
            for (int d0 = 0; d0 < 2; ++d0)
                ldsm4(a[d0][0], a[d0][1], a[d0][2], a[d0][3], ql_b + aoff + d0 * 32);
#pragma unroll
            for (int d0 = 0; d0 < 2; ++d0)
#pragma unroll
                for (int nt = 0; nt < 2; ++nt)
                    mma16816(s[nt], a[d0], &khf[d0][nt * 2]);

            // ---- mask + exp ----
            const int r0 = m0 + r_off;
            const int r1 = r0 + 8;
            const int rb0 = (r0 < SEQ) ? (r0 / 22) : -1;
            const int rb1 = (r1 < SEQ) ? (r1 / 22) : -1;

            float p[2][4];
#pragma unroll
            for (int nt = 0; nt < 2; ++nt) {
                const int tc0 = t0 + nt * 8 + c_off;
                const int tc1 = tc0 + 1;
                const int tb0 = nt ? tbA1 : tbA0;
                const int tb1 = nt ? tbB1 : tbB0;
                const float e0 = __expf(s[nt][0]);
                const float e1 = __expf(s[nt][1]);
                const float e2 = __expf(s[nt][2]);
                const float e3 = __expf(s[nt][3]);
                p[nt][0] = (rb0 == tb0 && r0 != tc0) ? 0.0f : e0;
                p[nt][1] = (rb0 == tb1 && r0 != tc1) ? 0.0f : e1;
                p[nt][2] = (rb1 == tb0 && r1 != tc0) ? 0.0f : e2;
                p[nt][3] = (rb1 == tb1 && r1 != tc1) ? 0.0f : e3;
            }
            lsum[i][0] += (p[0][0] + p[0][1]) + (p[1][0] + p[1][1]);
            lsum[i][1] += (p[0][2] + p[0][3]) + (p[1][2] + p[1][3]);

            // ---- repack S c-frag -> PV A-frag (hi/lo) ----
            uint32_t phi[4], plo[4];
#pragma unroll
            for (int nt = 0; nt < 2; ++nt)
#pragma unroll
                for (int hf = 0; hf < 2; ++hf) {
                    const float pa = p[nt][hf * 2], pb = p[nt][hf * 2 + 1];
                    __nv_bfloat162 hh = __floats2bfloat162_rn(pa, pb);
                    __nv_bfloat162 ll = __floats2bfloat162_rn(pa - __bfloat162float(hh.x),
                                                              pb - __bfloat162float(hh.y));
                    phi[nt * 2 + hf] = *(uint32_t*)&hh;
                    plo[nt * 2 + hf] = *(uint32_t*)&ll;
                }

            // ---- PV accumulate: 3 passes ----
#pragma unroll
            for (int dp = 0; dp < 2; ++dp)
#pragma unroll
                for (int nt = 0; nt < 2; ++nt) {
                    const int dt = dp * 2 + nt;
                    mma16816(accPV[i][dt], phi, &vhf[dp][nt * 2]);
                    mma16816(accPV[i][dt], plo, &vhf[dp][nt * 2]);
                    mma16816(accPV[i][dt], phi, &vlf[dp][nt * 2]);
                }
        }
    }

    // ---- reduce row sums across quad, normalize, store ----
#pragma unroll
    for (int i = 0; i < 3; ++i) {
#pragma unroll
        for (int j = 0; j < 2; ++j) {
            lsum[i][j] += __shfl_xor_sync(0xffffffffu, lsum[i][j], 1);
            lsum[i][j] += __shfl_xor_sync(0xffffffffu, lsum[i][j], 2);
        }
        const int m0 = (3 * w + i) * 16;
        const int r0 = m0 + r_off;
        const int r1 = r0 + 8;
        const float inv0 = 1.0f / lsum[i][0];
        const float inv1 = 1.0f / lsum[i][1];
        const int cb = h * H_DIM + c_off;
        if (r0 < SEQ) {
            float* o = out + ((size_t)b * SEQ + r0) * D_MODEL + cb;
#pragma unroll
            for (int dt = 0; dt < 4; ++dt)
                *(float2*)(o + dt * 8) = make_float2(accPV[i][dt][0] * inv0,
                                                     accPV[i][dt][1] * inv0);
        }
        if (r1 < SEQ) {
            float* o = out + ((size_t)b * SEQ + r1) * D_MODEL + cb;
#pragma unroll
            for (int dt = 0; dt < 4; ++dt)
                *(float2*)(o + dt * 8) = make_float2(accPV[i][dt][2] * inv1,
                                                     accPV[i][dt][3] * inv1);
        }
    }
}

// ---------------------------------------------------------------------------
extern "C" void kernel_launch(void* const* d_in, const int* in_sizes, int n_in,
                              void* d_out, int out_size)
{
    const float* x  = (const float*)d_in[0];
    const float* Wq = (const float*)d_in[1];
    const float* bq = (const float*)d_in[2];
    const float* Wk = (const float*)d_in[3];
    const float* bk = (const float*)d_in[4];
    const float* Wv = (const float*)d_in[5];
    const float* bv = (const float*)d_in[6];
    float* out = (float*)d_out;

    static int smem_set = 0;
    if (!smem_set) {
        cudaFuncSetAttribute(qkv_mma_kernel, cudaFuncAttributeMaxDynamicSharedMemorySize, SMTOT);
        cudaFuncSetAttribute(attn_mma_kernel, cudaFuncAttributeMaxDynamicSharedMemorySize, ASMEM_BYTES);
        smem_set = 1;
    }

    split_x_kernel<<<(M_TOTAL * D_IN) / (256 * 4), 256>>>(x);
    split_w_kernel<<<dim3(D_MODEL, 3), 128>>>(Wq, Wk, Wv);
    qkv_mma_kernel<<<dim3(M_TOTAL / 128, 6), 256, SMTOT>>>(bq, bk, bv);
    attn_mma_kernel<<<BATCH * H_NUM, 128, ASMEM_BYTES>>>(out);
}